// round 16
// baseline (speedup 1.0000x reference)
#include <cuda_runtime.h>
#include <cuda_fp16.h>
#include <cstdint>

#define NTOK 8192
#define DIM  2048
#define NE   8
#define NPAIR 28
#define MAXI 96
#define TM   128
#define TN   128
#define TK   32
#define NSTG 6
#define KITERS (DIM / TK)   // 64
#define GTOK 32             // tokens per gate block
#define GEMM_CTAS 296       // 2 per SM x 148 SMs

// ---------------- scratch (__device__ globals; no allocation) ----------------
__device__ __half g_Wp[(size_t)NPAIR * DIM * DIM];  // 28 fp16 pattern matrices (235 MB)
__device__ __half g_x16[(size_t)NTOK * DIM];        // fp16 x, token order (32 MB)
__device__ __half g_Xg[(size_t)NTOK * DIM];         // fp16 x, pattern-sorted (32 MB)
__device__ int   g_pid[NTOK];
__device__ int   g_perm[NTOK];
__device__ int   g_items[MAXI * 3];                 // (p28, m0, nrows)
__device__ int   g_total;
__device__ int   g_cnt[64];                         // zero-init; re-zeroed by scanA each run
__device__ int   g_cur[64];

__device__ const int c_pa[NPAIR] = {0,0,0,0,0,0,0,1,1,1,1,1,1,2,2,2,2,2,3,3,3,3,4,4,4,5,5,6};
__device__ const int c_pb[NPAIR] = {1,2,3,4,5,6,7,2,3,4,5,6,7,3,4,5,6,7,4,5,6,7,5,6,7,6,7,7};

// ---------------- helpers ----------------
__device__ __forceinline__ uint32_t h2u(__half2 h) {
    return *reinterpret_cast<uint32_t*>(&h);
}
__device__ __forceinline__ uint32_t smem_u32(const void* p) {
    uint32_t a;
    asm("{ .reg .u64 t; cvta.to.shared.u64 t, %1; cvt.u32.u64 %0, t; }" : "=r"(a) : "l"(p));
    return a;
}
__device__ __forceinline__ void cp16(uint32_t s, const void* g) {
    asm volatile("cp.async.cg.shared.global [%0], [%1], 16;" :: "r"(s), "l"(g) : "memory");
}
__device__ __forceinline__ void cp_commit() {
    asm volatile("cp.async.commit_group;" ::: "memory");
}
template <int N>
__device__ __forceinline__ void cp_wait() {
    asm volatile("cp.async.wait_group %0;" :: "n"(N) : "memory");
}
__device__ __forceinline__ void cp_wait_all() {
    asm volatile("cp.async.wait_all;" ::: "memory");
}
__device__ __forceinline__ void ldsm4(uint32_t* r, uint32_t a) {
    asm volatile("ldmatrix.sync.aligned.m8n8.x4.shared.b16 {%0,%1,%2,%3}, [%4];"
                 : "=r"(r[0]), "=r"(r[1]), "=r"(r[2]), "=r"(r[3]) : "r"(a));
}
__device__ __forceinline__ void mma16816(float* d, const uint32_t* a, uint32_t b0, uint32_t b1) {
    asm volatile("mma.sync.aligned.m16n8k16.row.col.f32.f16.f16.f32 "
        "{%0,%1,%2,%3}, {%4,%5,%6,%7}, {%8,%9}, {%0,%1,%2,%3};"
        : "+f"(d[0]), "+f"(d[1]), "+f"(d[2]), "+f"(d[3])
        : "r"(a[0]), "r"(a[1]), "r"(a[2]), "r"(a[3]), "r"(b0), "r"(b1));
}
// Knuth TwoSum merge: (hi,lo) += (p, e)  — exact error capture, branchless, fp32 only
__device__ __forceinline__ void df_add(float& hi, float& lo, float p, float e) {
    float s  = hi + p;
    float bb = s - hi;
    float err = (hi - (s - bb)) + (p - bb);
    hi = s;
    lo += err + e;
}

// ---------------- launch 0: gate1 (fp32 ranking + inline df64 redo + x->fp16 + count) ----------------
// grid = NTOK/GTOK = 256, block = 256, dyn smem = Wg(64KB) + 2 x-rows(16KB)
#define GATE_SMEM ((NE * DIM + 2 * DIM) * 4)
__global__ __launch_bounds__(256) void gate1_kernel(const float* __restrict__ x,
                                                    const float* __restrict__ Wg,
                                                    const float* __restrict__ bg) {
    extern __shared__ float sm[];
    float* sWg = sm;                 // [NE*DIM]
    float* xb  = sm + NE * DIM;      // [2][DIM]
    __shared__ float sh[NE], sl[NE];
    __shared__ int sredo;
    int tid = threadIdx.x, w = tid >> 5, lane = tid & 31;
    uint32_t xb_u32 = smem_u32(xb);

    for (int i = tid; i < NE * DIM; i += 256) sWg[i] = Wg[i];

    int t0 = blockIdx.x * GTOK;
    {   // prefetch token 0 (8KB = 512 x 16B; 2 chunks/thread)
        const float* xr = x + (size_t)t0 * DIM;
        cp16(xb_u32 + tid * 16, xr + tid * 4);
        cp16(xb_u32 + 4096 + tid * 16, xr + 1024 + tid * 4);
        cp_commit();
    }

    const float* wr = sWg + w * DIM;
    for (int tt = 0; tt < GTOK; tt++) {
        if (tt + 1 < GTOK) {
            const float* xr = x + (size_t)(t0 + tt + 1) * DIM;
            uint32_t d = xb_u32 + ((tt + 1) & 1) * 8192;
            cp16(d + tid * 16, xr + tid * 4);
            cp16(d + 4096 + tid * 16, xr + 1024 + tid * 4);
            cp_commit();
            cp_wait<1>();           // token tt's group complete
        } else {
            cp_wait_all();
        }
        __syncthreads();            // tt visible; Wg loaded (first iter)

        const float* xs = xb + (tt & 1) * DIM;
        float a0 = 0.f, a1 = 0.f, a2 = 0.f, a3 = 0.f;
#pragma unroll
        for (int t = 0; t < DIM / 128; t++) {
            int i = lane + t * 128;
            a0 = fmaf(xs[i],      wr[i],      a0);
            a1 = fmaf(xs[i + 32], wr[i + 32], a1);
            a2 = fmaf(xs[i + 64], wr[i + 64], a2);
            a3 = fmaf(xs[i + 96], wr[i + 96], a3);
        }
        float acc = (a0 + a1) + (a2 + a3);
#pragma unroll
        for (int o = 16; o; o >>= 1) acc += __shfl_xor_sync(0xffffffffu, acc, o);
        if (lane == 0) sh[w] = acc + bg[w];

        // emit fp16 copy of this token's row (xs stable during iter tt)
        {
            const float4* src = (const float4*)(xs + tid * 8);
            float4 v0 = src[0], v1 = src[1];
            uint4 o;
            o.x = h2u(__floats2half2_rn(v0.x, v0.y));
            o.y = h2u(__floats2half2_rn(v0.z, v0.w));
            o.z = h2u(__floats2half2_rn(v1.x, v1.y));
            o.w = h2u(__floats2half2_rn(v1.z, v1.w));
            ((uint4*)(g_x16 + (size_t)(t0 + tt) * DIM))[tid] = o;
        }
        __syncthreads();            // scores ready; compute on buf done (WAR gate)

        if (tid == 0) {
            int m1 = 0;
            for (int e = 1; e < NE; e++) if (sh[e] < sh[m1]) m1 = e;
            int m2 = -1;
            for (int e = 0; e < NE; e++) {
                if (e == m1) continue;
                if (m2 < 0 || sh[e] < sh[m2]) m2 = e;
            }
            float s3 = 3.4e38f;
            for (int e = 0; e < NE; e++) {
                if (e == m1 || e == m2) continue;
                if (sh[e] < s3) s3 = sh[e];
            }
            sredo = (s3 - sh[m2] < 1e-3f) ? 1 : 0;
        }
        __syncthreads();

        if (sredo) {
            // full-precision df64 redo on the resident xs
            float hi = 0.f, lo = 0.f;
            for (int i = lane; i < DIM; i += 32) {
                float a = xs[i], b2 = wr[i];
                float pp = a * b2;
                float ee = fmaf(a, b2, -pp);
                df_add(hi, lo, pp, ee);
            }
#pragma unroll
            for (int o = 16; o; o >>= 1) {
                float h2 = __shfl_xor_sync(0xffffffffu, hi, o);
                float l2 = __shfl_xor_sync(0xffffffffu, lo, o);
                df_add(hi, lo, h2, l2);
            }
            if (lane == 0) {
                df_add(hi, lo, bg[w], 0.f);
                float s2 = hi + lo;
                float t2 = lo - (s2 - hi);
                sh[w] = s2; sl[w] = t2;
            }
            __syncthreads();
        }

        if (tid == 0) {
            int m1, m2;
            if (sredo) {
                // exact lexicographic pick; ties -> larger index excluded
                m1 = 0;
                for (int e = 1; e < NE; e++) {
                    bool lt = (sh[e] < sh[m1]) || (sh[e] == sh[m1] && sl[e] < sl[m1]);
                    bool eq = (sh[e] == sh[m1] && sl[e] == sl[m1]);
                    if (lt || (eq && e > m1)) m1 = e;
                }
                m2 = -1;
                for (int e = 0; e < NE; e++) {
                    if (e == m1) continue;
                    if (m2 < 0) { m2 = e; continue; }
                    bool lt = (sh[e] < sh[m2]) || (sh[e] == sh[m2] && sl[e] < sl[m2]);
                    bool eq = (sh[e] == sh[m2] && sl[e] == sl[m2]);
                    if (lt || (eq && e > m2)) m2 = e;
                }
            } else {
                m1 = 0;
                for (int e = 1; e < NE; e++) if (sh[e] < sh[m1]) m1 = e;
                m2 = -1;
                for (int e = 0; e < NE; e++) {
                    if (e == m1) continue;
                    if (m2 < 0 || sh[e] < sh[m2]) m2 = e;
                }
            }
            int a = min(m1, m2), b = max(m1, m2);
            int pid = a * NE + b;
            g_pid[t0 + tt] = pid;
            atomicAdd(&g_cnt[pid], 1);
        }
    }
}

// ---------------- launch 1: scanA (prefix + items from g_cnt; re-zero g_cnt) ----------------
__global__ void scanA_kernel() {
    if (threadIdx.x == 0) {
        int rowoff = 0, t = 0;
        for (int p = 0; p < NPAIR; p++) {
            int pid = c_pa[p] * NE + c_pb[p];
            int c = g_cnt[pid];
            g_cur[pid] = rowoff;
            for (int r = 0; r < c && t < MAXI; r += TM) {
                g_items[3 * t]     = p;
                g_items[3 * t + 1] = rowoff + r;
                g_items[3 * t + 2] = min(TM, c - r);
                t++;
            }
            rowoff += c;
        }
        g_total = t;
    }
    __syncthreads();
    if (threadIdx.x < 64) g_cnt[threadIdx.x] = 0;   // reset for next graph replay
}

// ---------------- launch 2: permgather (claim perm slot + copy fp16 row) ----------------
__global__ __launch_bounds__(256) void permgather_kernel() {
    __shared__ int spos;
    int j = blockIdx.x;
    if (threadIdx.x == 0) {
        int pos = atomicAdd(&g_cur[g_pid[j]], 1);
        g_perm[pos] = j;
        spos = pos;
    }
    __syncthreads();
    int pos = spos;
    ((uint4*)(g_Xg + (size_t)pos * DIM))[threadIdx.x] =
        ((const uint4*)(g_x16 + (size_t)j * DIM))[threadIdx.x];
}

// ---------------- launch 3: build 28 fp16 pattern matrices ----------------
__global__ __launch_bounds__(256) void build_kernel(const float* __restrict__ We) {
    size_t i4 = (size_t)blockIdx.x * 256 + threadIdx.x;   // float4 index into DIM*DIM
    float4 v[NE];
    float4 s = make_float4(0.f, 0.f, 0.f, 0.f);
#pragma unroll
    for (int e = 0; e < NE; e++) {
        v[e] = ((const float4*)(We + (size_t)e * DIM * DIM))[i4];
        s.x += v[e].x; s.y += v[e].y; s.z += v[e].z; s.w += v[e].w;
    }
#pragma unroll
    for (int p = 0; p < NPAIR; p++) {
        int a = c_pa[p], b = c_pb[p];
        uint2 o;
        o.x = h2u(__floats2half2_rn(s.x - v[a].x - v[b].x, s.y - v[a].y - v[b].y));
        o.y = h2u(__floats2half2_rn(s.z - v[a].z - v[b].z, s.w - v[a].w - v[b].w));
        ((uint2*)(g_Wp + (size_t)p * DIM * DIM))[i4] = o;
    }
}

// ---------------- launch 4: persistent mma.sync fp16 GEMM ----------------
// 4 warps, warp tile 64x64, CTA tile 128x128, TK=32, NSTG=6, one sync per k-iter.
// 296 persistent CTAs loop over units u = item*16 + nblk.
#define STG_BYTES 16384
#define OFF_BIAS  (NSTG * STG_BYTES)
#define OFF_TOKS  (OFF_BIAS + 512)
#define SMEM_TOTAL (OFF_TOKS + 512)

__device__ __forceinline__ uint32_t swz(int row, int kc) {   // chunk swizzle, conflict-free ldmatrix
    return (uint32_t)(row * 64 + ((kc ^ ((row >> 1) & 3)) << 4));
}

__global__ __launch_bounds__(128, 2) void gemm_kernel(const float* __restrict__ be,
                                                      float* __restrict__ out) {
    extern __shared__ char smem[];
    uint32_t sb = smem_u32(smem);
    int tid = threadIdx.x, wid = tid >> 5, lane = tid & 31;
    float* sbias = (float*)(smem + OFF_BIAS);
    int*   stoks = (int*)(smem + OFF_TOKS);

    int m0w = (wid & 1) * 64, n0w = (wid >> 1) * 64;
    int crow = tid >> 2;        // 0..31
    int cchk = tid & 3;         // 0..3

    // unit-invariant ldmatrix smem offsets (stage-relative)
    uint32_t aoff[2][4], boff[2][4], dA[4];
#pragma unroll
    for (int kg = 0; kg < 2; kg++) {
#pragma unroll
        for (int mf = 0; mf < 4; mf++) {
            int row = m0w + mf * 16 + (lane & 7) + ((lane >> 3) & 1) * 8;
            int kc = kg * 2 + ((lane >> 4) & 1);
            aoff[kg][mf] = swz(row, kc);
        }
#pragma unroll
        for (int np = 0; np < 4; np++) {
            int nn = n0w + np * 16 + (lane & 7) + ((lane >> 4) & 1) * 8;
            int kc = kg * 2 + ((lane >> 3) & 1);
            boff[kg][np] = 8192u + swz(nn, kc);
        }
    }
#pragma unroll
    for (int ps = 0; ps < 4; ps++) dA[ps] = swz(crow + 32 * ps, cchk);

    int units = g_total * 16;
    for (int u = blockIdx.x; u < units; u += GEMM_CTAS) {
        int item = u >> 4;
        int n0 = (u & 15) * TN;
        int p     = g_items[3 * item];
        int m0    = g_items[3 * item + 1];
        int nrows = g_items[3 * item + 2];
        int ea = c_pa[p], eb = c_pb[p];

        __syncthreads();            // prior unit's epilogue reads done (WAR on stoks/sbias)
        {
            float bs = 0.f;
#pragma unroll
            for (int e = 0; e < NE; e++)
                if (e != ea && e != eb) bs += be[e * DIM + n0 + tid];
            sbias[tid] = bs;
            stoks[tid] = (tid < nrows) ? g_perm[m0 + tid] : -1;
        }

        const __half* srcA[4];
        const __half* srcB[4];
#pragma unroll
        for (int ps = 0; ps < 4; ps++) {
            int ra = min(m0 + crow + 32 * ps, NTOK - 1);
            srcA[ps] = g_Xg + (size_t)ra * DIM + cchk * 8;
            srcB[ps] = g_Wp + ((size_t)p * DIM + (n0 + crow + 32 * ps)) * DIM + cchk * 8;
        }

        float acc[4][8][4];
#pragma unroll
        for (int i = 0; i < 4; i++)
#pragma unroll
            for (int j = 0; j < 8; j++)
#pragma unroll
                for (int k = 0; k < 4; k++) acc[i][j][k] = 0.f;

        // prologue: issue stages 0..NSTG-2
#pragma unroll
        for (int s = 0; s < NSTG - 1; s++) {
            uint32_t st = sb + s * STG_BYTES;
            int ko = s * TK;
#pragma unroll
            for (int ps = 0; ps < 4; ps++) {
                cp16(st + dA[ps], srcA[ps] + ko);
                cp16(st + 8192 + dA[ps], srcB[ps] + ko);
            }
            cp_commit();
        }

#define COMPUTE_KT(kt_)                                                          \
    do {                                                                         \
        uint32_t st = sb + ((kt_) % NSTG) * STG_BYTES;                           \
        _Pragma("unroll")                                                        \
        for (int kg = 0; kg < 2; kg++) {                                         \
            uint32_t afr[4][4];                                                  \
            _Pragma("unroll")                                                    \
            for (int mf = 0; mf < 4; mf++) ldsm4(afr[mf], st + aoff[kg][mf]);    \
            uint32_t bfr[4][4];                                                  \
            _Pragma("unroll")                                                    \
            for (int np = 0; np < 4; np++) ldsm4(bfr[np], st + boff[kg][np]);    \
            _Pragma("unroll")                                                    \
            for (int mf = 0; mf < 4; mf++)                                       \
                _Pragma("unroll")                                                \
                for (int nf = 0; nf < 8; nf++)                                   \
                    mma16816(acc[mf][nf], afr[mf], bfr[nf >> 1][(nf & 1) * 2],   \
                             bfr[nf >> 1][(nf & 1) * 2 + 1]);                    \
        }                                                                        \
    } while (0)

        // main loop: one __syncthreads per k-iter
        for (int kt = 0; kt < KITERS - (NSTG - 1); kt++) {
            cp_wait<NSTG - 2>();    // this thread's stage-kt copies done
            __syncthreads();        // visibility + WAR for stage about to be rewritten
            {
                uint32_t st = sb + ((kt + NSTG - 1) % NSTG) * STG_BYTES;
                int ko = (kt + NSTG - 1) * TK;
#pragma unroll
                for (int ps = 0; ps < 4; ps++) {
                    cp16(st + dA[ps], srcA[ps] + ko);
                    cp16(st + 8192 + dA[ps], srcB[ps] + ko);
                }
                cp_commit();
            }
            COMPUTE_KT(kt);
        }
        // tail: all data already issued; drain once, then sync-free compute
        cp_wait_all();
        __syncthreads();
#pragma unroll
        for (int j = 0; j < NSTG - 1; j++) {
            int kt = KITERS - (NSTG - 1) + j;
            COMPUTE_KT(kt);
        }

        // epilogue: bias + scatter (stoks/sbias resident)
#pragma unroll
        for (int mf = 0; mf < 4; mf++) {
            int rbase = m0w + mf * 16 + (lane >> 2);
            int t0 = stoks[rbase], t1 = stoks[rbase + 8];
#pragma unroll
            for (int nf = 0; nf < 8; nf++) {
                int cbase = n0w + nf * 8 + (lane & 3) * 2;
                float b0 = sbias[cbase], b1 = sbias[cbase + 1];
                if (t0 >= 0) {
                    float2 o = make_float2(acc[mf][nf][0] + b0, acc[mf][nf][1] + b1);
                    *(float2*)(out + (size_t)t0 * DIM + n0 + cbase) = o;
                }
                if (t1 >= 0) {
                    float2 o = make_float2(acc[mf][nf][2] + b0, acc[mf][nf][3] + b1);
                    *(float2*)(out + (size_t)t1 * DIM + n0 + cbase) = o;
                }
            }
        }
    }
}

// ---------------- host ----------------
extern "C" void kernel_launch(void* const* d_in, const int* in_sizes, int n_in,
                              void* d_out, int out_size) {
    const float* x  = (const float*)d_in[0];
    const float* Wg = (const float*)d_in[1];
    const float* bg = (const float*)d_in[2];
    const float* We = (const float*)d_in[3];
    const float* be = (const float*)d_in[4];
    float* out = (float*)d_out;

    static bool init_done = false;
    if (!init_done) {
        cudaFuncSetAttribute(gemm_kernel, cudaFuncAttributeMaxDynamicSharedMemorySize, SMEM_TOTAL);
        cudaFuncSetAttribute(gate1_kernel, cudaFuncAttributeMaxDynamicSharedMemorySize, GATE_SMEM);
        init_done = true;
    }

    gate1_kernel<<<NTOK / GTOK, 256, GATE_SMEM>>>(x, Wg, bg);
    scanA_kernel<<<1, 64>>>();
    permgather_kernel<<<NTOK, 256>>>();
    build_kernel<<<DIM * DIM / (256 * 4), 256>>>(We);
    gemm_kernel<<<GEMM_CTAS, 128, SMEM_TOTAL>>>(be, out);
}

// round 17
// speedup vs baseline: 1.1230x; 1.1230x over previous
#include <cuda_runtime.h>
#include <cuda_fp16.h>
#include <cstdint>

#define NTOK 8192
#define DIM  2048
#define NE   8
#define NPAIR 28
#define MAXI 96
#define TM   128
#define TN   128
#define TK   32
#define NSTG 6
#define KITERS (DIM / TK)   // 64
#define GTOK 32             // tokens per gate block

// ---------------- scratch (__device__ globals; no allocation) ----------------
__device__ __half g_Wp[(size_t)NPAIR * DIM * DIM];  // 28 fp16 pattern matrices (235 MB)
__device__ __half g_x16[(size_t)NTOK * DIM];        // fp16 x, token order (32 MB)
__device__ __half g_Xg[(size_t)NTOK * DIM];         // fp16 x, pattern-sorted (32 MB)
__device__ int   g_pid[NTOK];
__device__ int   g_perm[NTOK];
__device__ int   g_items[MAXI * 3];                 // (p28, m0, nrows)
__device__ int   g_total;
__device__ int   g_cnt[64];                         // zero-init; re-zeroed by scanA each run
__device__ int   g_cur[64];

__device__ const int c_pa[NPAIR] = {0,0,0,0,0,0,0,1,1,1,1,1,1,2,2,2,2,2,3,3,3,3,4,4,4,5,5,6};
__device__ const int c_pb[NPAIR] = {1,2,3,4,5,6,7,2,3,4,5,6,7,3,4,5,6,7,4,5,6,7,5,6,7,6,7,7};

// ---------------- helpers ----------------
__device__ __forceinline__ uint32_t h2u(__half2 h) {
    return *reinterpret_cast<uint32_t*>(&h);
}
__device__ __forceinline__ uint32_t smem_u32(const void* p) {
    uint32_t a;
    asm("{ .reg .u64 t; cvta.to.shared.u64 t, %1; cvt.u32.u64 %0, t; }" : "=r"(a) : "l"(p));
    return a;
}
__device__ __forceinline__ void cp16(uint32_t s, const void* g) {
    asm volatile("cp.async.cg.shared.global [%0], [%1], 16;" :: "r"(s), "l"(g) : "memory");
}
__device__ __forceinline__ void cp_commit() {
    asm volatile("cp.async.commit_group;" ::: "memory");
}
template <int N>
__device__ __forceinline__ void cp_wait() {
    asm volatile("cp.async.wait_group %0;" :: "n"(N) : "memory");
}
__device__ __forceinline__ void cp_wait_all() {
    asm volatile("cp.async.wait_all;" ::: "memory");
}
__device__ __forceinline__ void ldsm4(uint32_t* r, uint32_t a) {
    asm volatile("ldmatrix.sync.aligned.m8n8.x4.shared.b16 {%0,%1,%2,%3}, [%4];"
                 : "=r"(r[0]), "=r"(r[1]), "=r"(r[2]), "=r"(r[3]) : "r"(a));
}
__device__ __forceinline__ void mma16816(float* d, const uint32_t* a, uint32_t b0, uint32_t b1) {
    asm volatile("mma.sync.aligned.m16n8k16.row.col.f32.f16.f16.f32 "
        "{%0,%1,%2,%3}, {%4,%5,%6,%7}, {%8,%9}, {%0,%1,%2,%3};"
        : "+f"(d[0]), "+f"(d[1]), "+f"(d[2]), "+f"(d[3])
        : "r"(a[0]), "r"(a[1]), "r"(a[2]), "r"(a[3]), "r"(b0), "r"(b1));
}
// Knuth TwoSum merge: (hi,lo) += (p, e)  — exact error capture, branchless, fp32 only
__device__ __forceinline__ void df_add(float& hi, float& lo, float p, float e) {
    float s  = hi + p;
    float bb = s - hi;
    float err = (hi - (s - bb)) + (p - bb);
    hi = s;
    lo += err + e;
}

// ---------------- launch 0: gate1 (fp32 ranking + inline df64 redo + x->fp16 + count) ----------------
// grid = NTOK/GTOK = 256, block = 256, dyn smem = Wg(64KB) + 2 x-rows(16KB)
#define GATE_SMEM ((NE * DIM + 2 * DIM) * 4)
__global__ __launch_bounds__(256) void gate1_kernel(const float* __restrict__ x,
                                                    const float* __restrict__ Wg,
                                                    const float* __restrict__ bg) {
    extern __shared__ float sm[];
    float* sWg = sm;                 // [NE*DIM]
    float* xb  = sm + NE * DIM;      // [2][DIM]
    __shared__ float sh[NE], sl[NE];
    __shared__ int sredo;
    int tid = threadIdx.x, w = tid >> 5, lane = tid & 31;
    uint32_t xb_u32 = smem_u32(xb);

    for (int i = tid; i < NE * DIM; i += 256) sWg[i] = Wg[i];

    int t0 = blockIdx.x * GTOK;
    {   // prefetch token 0 (8KB = 512 x 16B; 2 chunks/thread)
        const float* xr = x + (size_t)t0 * DIM;
        cp16(xb_u32 + tid * 16, xr + tid * 4);
        cp16(xb_u32 + 4096 + tid * 16, xr + 1024 + tid * 4);
        cp_commit();
    }

    const float* wr = sWg + w * DIM;
    for (int tt = 0; tt < GTOK; tt++) {
        if (tt + 1 < GTOK) {
            const float* xr = x + (size_t)(t0 + tt + 1) * DIM;
            uint32_t d = xb_u32 + ((tt + 1) & 1) * 8192;
            cp16(d + tid * 16, xr + tid * 4);
            cp16(d + 4096 + tid * 16, xr + 1024 + tid * 4);
            cp_commit();
            cp_wait<1>();           // token tt's group complete
        } else {
            cp_wait_all();
        }
        __syncthreads();            // tt visible; Wg loaded (first iter)

        const float* xs = xb + (tt & 1) * DIM;
        float a0 = 0.f, a1 = 0.f, a2 = 0.f, a3 = 0.f;
#pragma unroll
        for (int t = 0; t < DIM / 128; t++) {
            int i = lane + t * 128;
            a0 = fmaf(xs[i],      wr[i],      a0);
            a1 = fmaf(xs[i + 32], wr[i + 32], a1);
            a2 = fmaf(xs[i + 64], wr[i + 64], a2);
            a3 = fmaf(xs[i + 96], wr[i + 96], a3);
        }
        float acc = (a0 + a1) + (a2 + a3);
#pragma unroll
        for (int o = 16; o; o >>= 1) acc += __shfl_xor_sync(0xffffffffu, acc, o);
        if (lane == 0) sh[w] = acc + bg[w];

        // emit fp16 copy of this token's row (xs stable during iter tt)
        {
            const float4* src = (const float4*)(xs + tid * 8);
            float4 v0 = src[0], v1 = src[1];
            uint4 o;
            o.x = h2u(__floats2half2_rn(v0.x, v0.y));
            o.y = h2u(__floats2half2_rn(v0.z, v0.w));
            o.z = h2u(__floats2half2_rn(v1.x, v1.y));
            o.w = h2u(__floats2half2_rn(v1.z, v1.w));
            ((uint4*)(g_x16 + (size_t)(t0 + tt) * DIM))[tid] = o;
        }
        __syncthreads();            // scores ready; compute on buf done (WAR gate)

        if (tid == 0) {
            int m1 = 0;
            for (int e = 1; e < NE; e++) if (sh[e] < sh[m1]) m1 = e;
            int m2 = -1;
            for (int e = 0; e < NE; e++) {
                if (e == m1) continue;
                if (m2 < 0 || sh[e] < sh[m2]) m2 = e;
            }
            float s3 = 3.4e38f;
            for (int e = 0; e < NE; e++) {
                if (e == m1 || e == m2) continue;
                if (sh[e] < s3) s3 = sh[e];
            }
            sredo = (s3 - sh[m2] < 1e-3f) ? 1 : 0;
        }
        __syncthreads();

        if (sredo) {
            // full-precision df64 redo on the resident xs
            float hi = 0.f, lo = 0.f;
            for (int i = lane; i < DIM; i += 32) {
                float a = xs[i], b2 = wr[i];
                float pp = a * b2;
                float ee = fmaf(a, b2, -pp);
                df_add(hi, lo, pp, ee);
            }
#pragma unroll
            for (int o = 16; o; o >>= 1) {
                float h2 = __shfl_xor_sync(0xffffffffu, hi, o);
                float l2 = __shfl_xor_sync(0xffffffffu, lo, o);
                df_add(hi, lo, h2, l2);
            }
            if (lane == 0) {
                df_add(hi, lo, bg[w], 0.f);
                float s2 = hi + lo;
                float t2 = lo - (s2 - hi);
                sh[w] = s2; sl[w] = t2;
            }
            __syncthreads();
        }

        if (tid == 0) {
            int m1, m2;
            if (sredo) {
                // exact lexicographic pick; ties -> larger index excluded
                m1 = 0;
                for (int e = 1; e < NE; e++) {
                    bool lt = (sh[e] < sh[m1]) || (sh[e] == sh[m1] && sl[e] < sl[m1]);
                    bool eq = (sh[e] == sh[m1] && sl[e] == sl[m1]);
                    if (lt || (eq && e > m1)) m1 = e;
                }
                m2 = -1;
                for (int e = 0; e < NE; e++) {
                    if (e == m1) continue;
                    if (m2 < 0) { m2 = e; continue; }
                    bool lt = (sh[e] < sh[m2]) || (sh[e] == sh[m2] && sl[e] < sl[m2]);
                    bool eq = (sh[e] == sh[m2] && sl[e] == sl[m2]);
                    if (lt || (eq && e > m2)) m2 = e;
                }
            } else {
                m1 = 0;
                for (int e = 1; e < NE; e++) if (sh[e] < sh[m1]) m1 = e;
                m2 = -1;
                for (int e = 0; e < NE; e++) {
                    if (e == m1) continue;
                    if (m2 < 0 || sh[e] < sh[m2]) m2 = e;
                }
            }
            int a = min(m1, m2), b = max(m1, m2);
            int pid = a * NE + b;
            g_pid[t0 + tt] = pid;
            atomicAdd(&g_cnt[pid], 1);
        }
    }
}

// ---------------- launch 1: scanA (prefix + items from g_cnt; re-zero g_cnt) ----------------
__global__ void scanA_kernel() {
    if (threadIdx.x == 0) {
        int rowoff = 0, t = 0;
        for (int p = 0; p < NPAIR; p++) {
            int pid = c_pa[p] * NE + c_pb[p];
            int c = g_cnt[pid];
            g_cur[pid] = rowoff;
            for (int r = 0; r < c && t < MAXI; r += TM) {
                g_items[3 * t]     = p;
                g_items[3 * t + 1] = rowoff + r;
                g_items[3 * t + 2] = min(TM, c - r);
                t++;
            }
            rowoff += c;
        }
        g_total = t;
    }
    __syncthreads();
    if (threadIdx.x < 64) g_cnt[threadIdx.x] = 0;   // reset for next graph replay
}

// ---------------- launch 2: permgather (claim perm slot + copy fp16 row) ----------------
__global__ __launch_bounds__(256) void permgather_kernel() {
    __shared__ int spos;
    int j = blockIdx.x;
    if (threadIdx.x == 0) {
        int pos = atomicAdd(&g_cur[g_pid[j]], 1);
        g_perm[pos] = j;
        spos = pos;
    }
    __syncthreads();
    int pos = spos;
    ((uint4*)(g_Xg + (size_t)pos * DIM))[threadIdx.x] =
        ((const uint4*)(g_x16 + (size_t)j * DIM))[threadIdx.x];
}

// ---------------- launch 3: build 28 fp16 pattern matrices ----------------
__global__ __launch_bounds__(256) void build_kernel(const float* __restrict__ We) {
    size_t i4 = (size_t)blockIdx.x * 256 + threadIdx.x;   // float4 index into DIM*DIM
    float4 v[NE];
    float4 s = make_float4(0.f, 0.f, 0.f, 0.f);
#pragma unroll
    for (int e = 0; e < NE; e++) {
        v[e] = ((const float4*)(We + (size_t)e * DIM * DIM))[i4];
        s.x += v[e].x; s.y += v[e].y; s.z += v[e].z; s.w += v[e].w;
    }
#pragma unroll
    for (int p = 0; p < NPAIR; p++) {
        int a = c_pa[p], b = c_pb[p];
        uint2 o;
        o.x = h2u(__floats2half2_rn(s.x - v[a].x - v[b].x, s.y - v[a].y - v[b].y));
        o.y = h2u(__floats2half2_rn(s.z - v[a].z - v[b].z, s.w - v[a].w - v[b].w));
        ((uint2*)(g_Wp + (size_t)p * DIM * DIM))[i4] = o;
    }
}

// ---------------- launch 4: mma.sync fp16 GEMM (one CTA per tile) ----------------
// 4 warps, warp tile 64x64, CTA tile 128x128, TK=32, NSTG=6, one sync per k-iter.
// grid = (DIM/TN, MAXI): x = n-block, y = item.
#define STG_BYTES 16384
#define OFF_BIAS  (NSTG * STG_BYTES)
#define OFF_TOKS  (OFF_BIAS + 512)
#define SMEM_TOTAL (OFF_TOKS + 512)

__device__ __forceinline__ uint32_t swz(int row, int kc) {   // chunk swizzle, conflict-free ldmatrix
    return (uint32_t)(row * 64 + ((kc ^ ((row >> 1) & 3)) << 4));
}

__global__ __launch_bounds__(128, 2) void gemm_kernel(const float* __restrict__ be,
                                                      float* __restrict__ out) {
    int item = blockIdx.y;
    if (item >= g_total) return;
    extern __shared__ char smem[];
    uint32_t sb = smem_u32(smem);
    int tid = threadIdx.x, wid = tid >> 5, lane = tid & 31;

    int p     = g_items[3 * item];
    int m0    = g_items[3 * item + 1];
    int nrows = g_items[3 * item + 2];
    int ea = c_pa[p], eb = c_pb[p];
    int n0 = blockIdx.x * TN;

    // bias + token list into smem (outside the pipeline region)
    float* sbias = (float*)(smem + OFF_BIAS);
    int*   stoks = (int*)(smem + OFF_TOKS);
    {
        float bs = 0.f;
#pragma unroll
        for (int e = 0; e < NE; e++)
            if (e != ea && e != eb) bs += be[e * DIM + n0 + tid];
        sbias[tid] = bs;
        stoks[tid] = (tid < nrows) ? g_perm[m0 + tid] : -1;
    }

    // cp.async mapping: 4 passes of 32 rows; 4 chunks of 16B per row
    int crow = tid >> 2;        // 0..31
    int cchk = tid & 3;         // 0..3
    const __half* srcA[4];
    const __half* srcB[4];
    uint32_t dA[4];
#pragma unroll
    for (int ps = 0; ps < 4; ps++) {
        int ra = min(m0 + crow + 32 * ps, NTOK - 1);
        srcA[ps] = g_Xg + (size_t)ra * DIM + cchk * 8;
        srcB[ps] = g_Wp + ((size_t)p * DIM + (n0 + crow + 32 * ps)) * DIM + cchk * 8;
        dA[ps] = swz(crow + 32 * ps, cchk);
    }

    float acc[4][8][4];
#pragma unroll
    for (int i = 0; i < 4; i++)
#pragma unroll
        for (int j = 0; j < 8; j++)
#pragma unroll
            for (int k = 0; k < 4; k++) acc[i][j][k] = 0.f;

    // prologue: issue stages 0..NSTG-2
#pragma unroll
    for (int s = 0; s < NSTG - 1; s++) {
        uint32_t st = sb + s * STG_BYTES;
        int ko = s * TK;
#pragma unroll
        for (int ps = 0; ps < 4; ps++) {
            cp16(st + dA[ps], srcA[ps] + ko);
            cp16(st + 8192 + dA[ps], srcB[ps] + ko);
        }
        cp_commit();
    }

    int m0w = (wid & 1) * 64, n0w = (wid >> 1) * 64;
    // precomputed ldmatrix smem offsets (stage-relative)
    uint32_t aoff[2][4], boff[2][4];
#pragma unroll
    for (int kg = 0; kg < 2; kg++) {
#pragma unroll
        for (int mf = 0; mf < 4; mf++) {
            int row = m0w + mf * 16 + (lane & 7) + ((lane >> 3) & 1) * 8;
            int kc = kg * 2 + ((lane >> 4) & 1);
            aoff[kg][mf] = swz(row, kc);
        }
#pragma unroll
        for (int np = 0; np < 4; np++) {
            int nn = n0w + np * 16 + (lane & 7) + ((lane >> 4) & 1) * 8;
            int kc = kg * 2 + ((lane >> 3) & 1);
            boff[kg][np] = 8192u + swz(nn, kc);
        }
    }

#define COMPUTE_KT(kt_)                                                          \
    do {                                                                         \
        uint32_t st = sb + ((kt_) % NSTG) * STG_BYTES;                           \
        _Pragma("unroll")                                                        \
        for (int kg = 0; kg < 2; kg++) {                                         \
            uint32_t afr[4][4];                                                  \
            _Pragma("unroll")                                                    \
            for (int mf = 0; mf < 4; mf++) ldsm4(afr[mf], st + aoff[kg][mf]);    \
            uint32_t bfr[4][4];                                                  \
            _Pragma("unroll")                                                    \
            for (int np = 0; np < 4; np++) ldsm4(bfr[np], st + boff[kg][np]);    \
            _Pragma("unroll")                                                    \
            for (int mf = 0; mf < 4; mf++)                                       \
                _Pragma("unroll")                                                \
                for (int nf = 0; nf < 8; nf++)                                   \
                    mma16816(acc[mf][nf], afr[mf], bfr[nf >> 1][(nf & 1) * 2],   \
                             bfr[nf >> 1][(nf & 1) * 2 + 1]);                    \
        }                                                                        \
    } while (0)

    // main loop: one __syncthreads per k-iter
    for (int kt = 0; kt < KITERS - (NSTG - 1); kt++) {
        cp_wait<NSTG - 2>();        // this thread's stage-kt copies done
        __syncthreads();            // visibility + WAR for stage about to be rewritten
        {
            uint32_t st = sb + ((kt + NSTG - 1) % NSTG) * STG_BYTES;
            int ko = (kt + NSTG - 1) * TK;
#pragma unroll
            for (int ps = 0; ps < 4; ps++) {
                cp16(st + dA[ps], srcA[ps] + ko);
                cp16(st + 8192 + dA[ps], srcB[ps] + ko);
            }
            cp_commit();
        }
        COMPUTE_KT(kt);
    }
    // tail: all data already issued; drain once, then sync-free compute
    cp_wait_all();
    __syncthreads();
#pragma unroll
    for (int j = 0; j < NSTG - 1; j++) {
        int kt = KITERS - (NSTG - 1) + j;
        COMPUTE_KT(kt);
    }

    // epilogue: bias + scatter (stoks/sbias resident)
#pragma unroll
    for (int mf = 0; mf < 4; mf++) {
        int rbase = m0w + mf * 16 + (lane >> 2);
        int t0 = stoks[rbase], t1 = stoks[rbase + 8];
#pragma unroll
        for (int nf = 0; nf < 8; nf++) {
            int cbase = n0w + nf * 8 + (lane & 3) * 2;
            float b0 = sbias[cbase], b1 = sbias[cbase + 1];
            if (t0 >= 0) {
                float2 o = make_float2(acc[mf][nf][0] + b0, acc[mf][nf][1] + b1);
                *(float2*)(out + (size_t)t0 * DIM + n0 + cbase) = o;
            }
            if (t1 >= 0) {
                float2 o = make_float2(acc[mf][nf][2] + b0, acc[mf][nf][3] + b1);
                *(float2*)(out + (size_t)t1 * DIM + n0 + cbase) = o;
            }
        }
    }
}

// ---------------- host ----------------
extern "C" void kernel_launch(void* const* d_in, const int* in_sizes, int n_in,
                              void* d_out, int out_size) {
    const float* x  = (const float*)d_in[0];
    const float* Wg = (const float*)d_in[1];
    const float* bg = (const float*)d_in[2];
    const float* We = (const float*)d_in[3];
    const float* be = (const float*)d_in[4];
    float* out = (float*)d_out;

    static bool init_done = false;
    if (!init_done) {
        cudaFuncSetAttribute(gemm_kernel, cudaFuncAttributeMaxDynamicSharedMemorySize, SMEM_TOTAL);
        cudaFuncSetAttribute(gate1_kernel, cudaFuncAttributeMaxDynamicSharedMemorySize, GATE_SMEM);
        init_done = true;
    }

    gate1_kernel<<<NTOK / GTOK, 256, GATE_SMEM>>>(x, Wg, bg);
    scanA_kernel<<<1, 64>>>();
    permgather_kernel<<<NTOK, 256>>>();
    build_kernel<<<DIM * DIM / (256 * 4), 256>>>(We);
    dim3 grid(DIM / TN, MAXI);
    gemm_kernel<<<grid, 128, SMEM_TOTAL>>>(be, out);
}